// round 16
// baseline (speedup 1.0000x reference)
#include <cuda_runtime.h>
#include <cuda_bf16.h>
#include <cuda_fp16.h>
#include <cstdint>

#define N_NODES 50000
#define N_EDGES 800000

// ---------------- scratch (static device globals; no allocation) ----------------
__device__ unsigned long long g_degcnt[N_NODES];  // {count:24 | sum_w fixed 2^-32:40}
__device__ float g_dinv[N_NODES];
__device__ int   g_rowoff[N_NODES];
__device__ int   g_rowend[N_NODES];
__device__ int   g_cursor[N_NODES];
__device__ uint32_t g_epack[N_EDGES];    // {col:16 | lw:fp16}, lw = -w*dinv_r*dinv_c
__device__ float g_Us[N_NODES * 128];    // f32 self channels [Z0 | R0]
__device__ uint32_t g_Ug1[N_NODES * 32]; // fp16 pairs, U1 (z-gather), 128B/node
__device__ uint32_t g_Ug2[N_NODES * 32]; // fp16 pairs, U2 (r-gather), 128B/node
__device__ float g_Vs[N_NODES * 64];     // f32 self [H0]
__device__ __half g_Vg[N_NODES * 64];    // fp16 gathered [U3]
__device__ float g_zb[N_NODES * 64];
__device__ float g_rhb[N_NODES * 64];
__device__ __nv_bfloat16 g_Wbhi[6 * 64 * 128];  // [mat][n][k] transposed weights, bf16 hi
__device__ __nv_bfloat16 g_Wblo[6 * 64 * 128];  // bf16 residual
__device__ int   g_is64;
__device__ int   g_counter;

// ---------------- host-side stream/event objects (created at load; host-only) ----
struct ForkCtx {
    cudaStream_t s2 = 0;
    cudaEvent_t evF = 0, evJ = 0, evR = 0, evZ = 0;
    ForkCtx() {
        if (cudaStreamCreateWithFlags(&s2, cudaStreamNonBlocking) != cudaSuccess) s2 = 0;
        cudaEventCreateWithFlags(&evF, cudaEventDisableTiming);
        cudaEventCreateWithFlags(&evJ, cudaEventDisableTiming);
        cudaEventCreateWithFlags(&evR, cudaEventDisableTiming);
        cudaEventCreateWithFlags(&evZ, cudaEventDisableTiming);
    }
};
static ForkCtx g_fork;

// ---------------- helpers ----------------
__device__ __forceinline__ uint32_t smem_u32(const void* p) {
    uint32_t a;
    asm("{ .reg .u64 t; cvta.to.shared.u64 t, %1; cvt.u32.u64 %0, t; }" : "=r"(a) : "l"(p));
    return a;
}
__device__ __forceinline__ uint32_t pack_bf16x2(float lo, float hi) {
    __nv_bfloat162 t = __floats2bfloat162_rn(lo, hi);
    return *(uint32_t*)&t;
}
__device__ __forceinline__ uint32_t pack_half2(float a, float b) {
    __half2 t = __floats2half2_rn(a, b);
    return *(uint32_t*)&t;
}
__device__ __forceinline__ float2 unpack_half2(uint32_t v) {
    return __half22float2(*(__half2*)&v);
}
__device__ __forceinline__ float ew_f(uint32_t E) {
    return __half2float(__ushort_as_half((unsigned short)(E & 0xFFFF)));
}
__device__ __forceinline__ void ldsm4(uint32_t a[4], uint32_t addr) {
    asm volatile("ldmatrix.sync.aligned.m8n8.x4.shared.b16 {%0,%1,%2,%3}, [%4];"
                 : "=r"(a[0]), "=r"(a[1]), "=r"(a[2]), "=r"(a[3]) : "r"(addr));
}
__device__ __forceinline__ void mma_bf16(float c[4], const uint32_t a[4], const uint32_t b[2]) {
    asm volatile("mma.sync.aligned.m16n8k16.row.col.f32.bf16.bf16.f32 "
                 "{%0,%1,%2,%3}, {%4,%5,%6,%7}, {%8,%9}, {%0,%1,%2,%3};"
                 : "+f"(c[0]), "+f"(c[1]), "+f"(c[2]), "+f"(c[3])
                 : "r"(a[0]), "r"(a[1]), "r"(a[2]), "r"(a[3]), "r"(b[0]), "r"(b[1]));
}
__device__ __forceinline__ int edge_idx(const void* ei, int pos) {
    if (g_is64) return (int)((const long long*)ei)[pos];
    return ((const int*)ei)[pos];
}

// ---------------- chain A kernel 1: zero accumulators + sniff index dtype ----------------
__global__ void k_init(const void* ei) {
    int i = blockIdx.x * 256 + threadIdx.x;
    if (i < N_NODES) g_degcnt[i] = 0ull;
    if (i == 0) {
        g_counter = 0;
        const int* p = (const int*)ei;
        int nz = 0;
#pragma unroll 8
        for (int j = 0; j < 256; j++) nz |= p[2 * j + 1];
        g_is64 = (nz == 0) ? 1 : 0;
    }
}

// ---------------- chain B kernel 1: weight transpose + split to bf16 hi/lo ----------------
__global__ void k_wprep(const float* __restrict__ Wz, const float* __restrict__ Wr,
                        const float* __restrict__ Wh) {
    int i = blockIdx.x * 256 + threadIdx.x;
    if (i >= 6 * 8192) return;
    int m = i >> 13;
    int r = i & 8191;
    int n = r >> 7;
    int k = r & 127;
    const float* W = (m < 2) ? Wz : (m < 4) ? Wr : Wh;
    float v = W[(m & 1) * 8192 + k * 64 + n];
    __nv_bfloat16 hi = __float2bfloat16(v);
    g_Wbhi[i] = hi;
    g_Wblo[i] = __float2bfloat16(v - __bfloat162float(hi));
}

// ---------------- chain A kernel 2: packed degree+count, 2 edges/thread ----------------
__global__ void k_deg(const void* ei, const float* __restrict__ w) {
    int e = (blockIdx.x * blockDim.x + threadIdx.x) * 2;
    if (e >= N_EDGES) return;
    int r0 = edge_idx(ei, e);
    float w0 = w[e];
    unsigned long long v0 = (1ull << 40) | (unsigned long long)(w0 * 4294967296.0f);
    if (e + 1 < N_EDGES) {
        int r1 = edge_idx(ei, e + 1);
        float w1 = w[e + 1];
        unsigned long long v1 = (1ull << 40) | (unsigned long long)(w1 * 4294967296.0f);
        atomicAdd(&g_degcnt[r0], v0);
        atomicAdd(&g_degcnt[r1], v1);
    } else {
        atomicAdd(&g_degcnt[r0], v0);
    }
}

// ---------------- chain A kernel 3: dinv + unordered segment assignment ----------------
__global__ void k_blockscan() {
    int i = blockIdx.x * 256 + threadIdx.x;
    int lane = threadIdx.x & 31, w = threadIdx.x >> 5;
    int v = 0;
    if (i < N_NODES) {
        unsigned long long dc = g_degcnt[i];
        v = (int)(dc >> 40);
        float d = (float)(dc & 0xFFFFFFFFFFull) * (1.0f / 4294967296.0f);
        g_dinv[i] = (d > 0.f) ? rsqrtf(d) : 0.f;
    }
    int s = v;
#pragma unroll
    for (int o = 1; o < 32; o <<= 1) {
        int t = __shfl_up_sync(0xFFFFFFFFu, s, o);
        if (lane >= o) s += t;
    }
    __shared__ int wsum[8];
    __shared__ int base;
    if (lane == 31) wsum[w] = s;
    __syncthreads();
    if (w == 0 && lane < 8) {
        int t = wsum[lane];
#pragma unroll
        for (int o = 1; o < 8; o <<= 1) {
            int u = __shfl_up_sync(0xFFu, t, o);
            if (lane >= o) t += u;
        }
        wsum[lane] = t;
        if (lane == 7) base = atomicAdd(&g_counter, t);
    }
    __syncthreads();
    int excl = s - v + ((w > 0) ? wsum[w - 1] : 0);
    if (i < N_NODES) {
        int st = base + excl;
        g_rowoff[i] = st;
        g_cursor[i] = st;
        g_rowend[i] = st + v;
    }
}

// ---------------- chain A kernel 4: CSR scatter, 2 edges/thread; norm folded into lw ----
__global__ void k_csr(const void* ei, const float* __restrict__ w) {
    int e = (blockIdx.x * blockDim.x + threadIdx.x) * 2;
    if (e >= N_EDGES) return;
    int r0 = edge_idx(ei, e);
    int c0 = edge_idx(ei, N_EDGES + e);
    float lw0 = -w[e] * g_dinv[r0] * g_dinv[c0];
    if (e + 1 < N_EDGES) {
        int r1 = edge_idx(ei, e + 1);
        int c1 = edge_idx(ei, N_EDGES + e + 1);
        float lw1 = -w[e + 1] * g_dinv[r1] * g_dinv[c1];
        int p0 = atomicAdd(&g_cursor[r0], 1);
        int p1 = atomicAdd(&g_cursor[r1], 1);
        g_epack[p0] = ((uint32_t)c0 << 16) | (uint32_t)__half_as_ushort(__float2half(lw0));
        g_epack[p1] = ((uint32_t)c1 << 16) | (uint32_t)__half_as_ushort(__float2half(lw1));
    } else {
        int p0 = atomicAdd(&g_cursor[r0], 1);
        g_epack[p0] = ((uint32_t)c0 << 16) | (uint32_t)__half_as_ushort(__float2half(lw0));
    }
}

// ---------------- mma.sync bf16-split GEMM: 128 rows x 128 cols x K=128 per CTA ----
__global__ void __launch_bounds__(256, 1) k_mgemm(
    const float* __restrict__ src0, const float* __restrict__ src1x, int use_rhb,
    int wb, int dst_sel) {
    extern __shared__ char sm[];
    const int AH = 0, AL = 32768, BH = 65536, BL = 98304;  // each 128 x 256B
    const int tid = threadIdx.x;
    const int lane = tid & 31, w = tid >> 5;
    const int rowBase = blockIdx.x * 128;
    const float* src1 = use_rhb ? g_rhb : src1x;
    const int matBase = wb + blockIdx.y * 2;

    // ---- load A ----
    {
        int row = tid & 127, half = tid >> 7;
        int gr = rowBase + row;
        const float* s = half ? src1 : src0;
        const float4* sp = (const float4*)(s + (size_t)gr * 64);
        char* ah = sm + AH + row * 256;
        char* al = sm + AL + row * 256;
        int rsw = row & 7;
#pragma unroll
        for (int i = 0; i < 8; i++) {
            float4 v0 = make_float4(0.f, 0.f, 0.f, 0.f), v1 = v0;
            if (gr < N_NODES) { v0 = sp[2 * i]; v1 = sp[2 * i + 1]; }
            int kc = half * 8 + i;
            int off = ((kc ^ rsw) << 4);
            uint4 hi, lo;
            hi.x = pack_bf16x2(v0.x, v0.y); hi.y = pack_bf16x2(v0.z, v0.w);
            hi.z = pack_bf16x2(v1.x, v1.y); hi.w = pack_bf16x2(v1.z, v1.w);
            float rx = v0.x - __bfloat162float(__float2bfloat16(v0.x));
            float ry = v0.y - __bfloat162float(__float2bfloat16(v0.y));
            float rz = v0.z - __bfloat162float(__float2bfloat16(v0.z));
            float rw = v0.w - __bfloat162float(__float2bfloat16(v0.w));
            lo.x = pack_bf16x2(rx, ry); lo.y = pack_bf16x2(rz, rw);
            rx = v1.x - __bfloat162float(__float2bfloat16(v1.x));
            ry = v1.y - __bfloat162float(__float2bfloat16(v1.y));
            rz = v1.z - __bfloat162float(__float2bfloat16(v1.z));
            rw = v1.w - __bfloat162float(__float2bfloat16(v1.w));
            lo.z = pack_bf16x2(rx, ry); lo.w = pack_bf16x2(rz, rw);
            *(uint4*)(ah + off) = hi;
            *(uint4*)(al + off) = lo;
        }
    }
    // ---- load B ----
#pragma unroll
    for (int j = 0; j < 8; j++) {
        int idx = tid + j * 256;
        int mat = idx >> 10, rest = idx & 1023;
        int n = rest >> 4, kc = rest & 15;
        int nn = mat * 64 + n;
        size_t gsi = (size_t)(matBase + mat) * 8192 + n * 128 + kc * 8;
        uint4 hv = *(const uint4*)(g_Wbhi + gsi);
        uint4 lv = *(const uint4*)(g_Wblo + gsi);
        int off = nn * 256 + (((kc ^ (nn & 7))) << 4);
        *(uint4*)(sm + BH + off) = hv;
        *(uint4*)(sm + BL + off) = lv;
    }
    __syncthreads();

    // ---- per-warp tile: rows (w&3)*32, mat = w>>2 ----
    const int Rw = (w & 3) * 32;
    const int matSel = w >> 2;
    const int NBw = matSel * 64;
    const uint32_t smb = smem_u32(sm);
    const int tile = lane >> 3, l7 = lane & 7;
    int a_kbit = tile >> 1;
    int a_row0 = Rw + ((tile & 1) << 3) + l7;
    int a_row1 = a_row0 + 16;
    uint32_t aBase0 = smb + AH + a_row0 * 256, aSw0 = (uint32_t)(a_row0 & 7);
    uint32_t aBase1 = smb + AH + a_row1 * 256, aSw1 = (uint32_t)(a_row1 & 7);
    int b_kbit = tile & 1;
    int b_nloc = ((tile >> 1) << 3) + l7;
    uint32_t bBase[4], bSw[4];
#pragma unroll
    for (int ng = 0; ng < 4; ng++) {
        int n = NBw + ng * 16 + b_nloc;
        bBase[ng] = smb + BH + n * 256;
        bSw[ng] = (uint32_t)(n & 7);
    }

    float C[2][4][2][4];
#pragma unroll
    for (int a = 0; a < 2; a++)
#pragma unroll
        for (int b = 0; b < 4; b++)
#pragma unroll
            for (int c = 0; c < 2; c++)
#pragma unroll
                for (int d = 0; d < 4; d++) C[a][b][c][d] = 0.f;

#pragma unroll
    for (int ks = 0; ks < 8; ks++) {
        int ks2 = ks * 2;
        uint32_t akc = (uint32_t)((ks2 + a_kbit));
        uint32_t bkc = (uint32_t)((ks2 + b_kbit));
        uint32_t Ah[2][4], Al[2][4];
        ldsm4(Ah[0], aBase0 + ((akc ^ aSw0) << 4));
        ldsm4(Ah[1], aBase1 + ((akc ^ aSw1) << 4));
        ldsm4(Al[0], aBase0 + 32768 + ((akc ^ aSw0) << 4));
        ldsm4(Al[1], aBase1 + 32768 + ((akc ^ aSw1) << 4));
        uint32_t Bh[4][4], Bl[4][4];
#pragma unroll
        for (int ng = 0; ng < 4; ng++) {
            ldsm4(Bh[ng], bBase[ng] + ((bkc ^ bSw[ng]) << 4));
            ldsm4(Bl[ng], bBase[ng] + 32768 + ((bkc ^ bSw[ng]) << 4));
        }
#pragma unroll
        for (int mt = 0; mt < 2; mt++)
#pragma unroll
            for (int ng = 0; ng < 4; ng++) {
                mma_bf16(C[mt][ng][0], Ah[mt], &Bh[ng][0]);
                mma_bf16(C[mt][ng][1], Ah[mt], &Bh[ng][2]);
                mma_bf16(C[mt][ng][0], Ah[mt], &Bl[ng][0]);
                mma_bf16(C[mt][ng][1], Ah[mt], &Bl[ng][2]);
                mma_bf16(C[mt][ng][0], Al[mt], &Bh[ng][0]);
                mma_bf16(C[mt][ng][1], Al[mt], &Bh[ng][2]);
            }
    }

    // ---- epilogue: self -> f32; gathered -> fp16 (by selects Ug1/Ug2 for GEMM1) ----
    {
        int by = blockIdx.y;
        int ldS = dst_sel ? 64 : 128;
        float* fdst = dst_sel ? g_Vs : g_Us;
        uint32_t* ug = (by == 0) ? g_Ug1 : g_Ug2;
        int colBase = by * 64;
        int q = lane >> 2, tg = lane & 3;
#pragma unroll
        for (int mt = 0; mt < 2; mt++) {
            int r0 = rowBase + Rw + mt * 16 + q;
#pragma unroll
            for (int ng = 0; ng < 4; ng++)
#pragma unroll
                for (int sub = 0; sub < 2; sub++) {
                    int lcol = ng * 16 + sub * 8 + tg * 2;
                    if (matSel == 0) {
                        float* d0 = &fdst[(size_t)r0 * ldS + colBase + lcol];
                        if (r0 < N_NODES)
                            *(float2*)d0 = make_float2(C[mt][ng][sub][0], C[mt][ng][sub][1]);
                        if (r0 + 8 < N_NODES)
                            *(float2*)(d0 + 8 * ldS) = make_float2(C[mt][ng][sub][2], C[mt][ng][sub][3]);
                    } else if (dst_sel == 0) {
                        uint32_t* d0 = &ug[(size_t)r0 * 32 + (lcol >> 1)];
                        if (r0 < N_NODES)
                            d0[0] = pack_half2(C[mt][ng][sub][0], C[mt][ng][sub][1]);
                        if (r0 + 8 < N_NODES)
                            d0[8 * 32] = pack_half2(C[mt][ng][sub][2], C[mt][ng][sub][3]);
                    } else {
                        __half* d0 = &g_Vg[(size_t)r0 * 64 + lcol];
                        if (r0 < N_NODES)
                            *(uint32_t*)d0 = pack_half2(C[mt][ng][sub][0], C[mt][ng][sub][1]);
                        if (r0 + 8 < N_NODES)
                            *(uint32_t*)(d0 + 8 * 64) = pack_half2(C[mt][ng][sub][2], C[mt][ng][sub][3]);
                    }
                }
        }
    }
}

// ---------------- generic 8x-unrolled gather core (one 128B line per node) ----------
template <typename F>
__device__ __forceinline__ float2 gather_row(const uint32_t* __restrict__ buf,
                                             int s, int e, int lane, F idx_of) {
    float ax = 0.f, ay = 0.f;
    int i = s;
    for (; i + 8 <= e; i += 8) {
        uint32_t E[8], V[8];
#pragma unroll
        for (int j = 0; j < 8; j++) E[j] = g_epack[i + j];
#pragma unroll
        for (int j = 0; j < 8; j++) V[j] = buf[idx_of(E[j]) + lane];
#pragma unroll
        for (int j = 0; j < 8; j++) {
            float w = ew_f(E[j]);
            float2 u = unpack_half2(V[j]);
            ax += w * u.x; ay += w * u.y;
        }
    }
    if (i + 4 <= e) {
        uint32_t E[4], V[4];
#pragma unroll
        for (int j = 0; j < 4; j++) E[j] = g_epack[i + j];
#pragma unroll
        for (int j = 0; j < 4; j++) V[j] = buf[idx_of(E[j]) + lane];
#pragma unroll
        for (int j = 0; j < 4; j++) {
            float w = ew_f(E[j]);
            float2 u = unpack_half2(V[j]);
            ax += w * u.x; ay += w * u.y;
        }
        i += 4;
    }
    for (; i < e; i++) {
        uint32_t E = g_epack[i];
        uint32_t v = buf[idx_of(E) + lane];
        float w = ew_f(E);
        float2 u = unpack_half2(v);
        ax += w * u.x; ay += w * u.y;
    }
    return make_float2(ax, ay);
}

struct Idx32 { __device__ size_t operator()(uint32_t E) const { return (size_t)(E >> 16) * 32; } };

// ---------------- prop1r: gather U2 only -> r gate -> rhb (critical path) ----------
__global__ void k_prop1r(const float* __restrict__ h, const float* __restrict__ br) {
    int gw = (blockIdx.x * blockDim.x + threadIdx.x) >> 5;
    int lane = threadIdx.x & 31;
    if (gw >= N_NODES) return;
    float2 a = gather_row(g_Ug2, g_rowoff[gw], g_rowend[gw], lane, Idx32());
    int co = lane * 2;
    float2 r0 = *(const float2*)&g_Us[(size_t)gw * 128 + 64 + co];
    float2 br2 = *(const float2*)&br[co];
    float rx = 1.f / (1.f + __expf(-(r0.x + br2.x + a.x)));
    float ry = 1.f / (1.f + __expf(-(r0.y + br2.y + a.y)));
    float2 hh = *(const float2*)&h[gw * 64 + co];
    *(float2*)&g_rhb[gw * 64 + co] = make_float2(rx * hh.x, ry * hh.y);
}

// ---------------- prop1z: gather U1 only -> z gate (overlaps GEMM2) ----------------
__global__ void k_prop1z(const float* __restrict__ bz) {
    int gw = (blockIdx.x * blockDim.x + threadIdx.x) >> 5;
    int lane = threadIdx.x & 31;
    if (gw >= N_NODES) return;
    float2 a = gather_row(g_Ug1, g_rowoff[gw], g_rowend[gw], lane, Idx32());
    int co = lane * 2;
    float2 z0 = *(const float2*)&g_Us[(size_t)gw * 128 + co];
    float2 bz2 = *(const float2*)&bz[co];
    float zx = 1.f / (1.f + __expf(-(z0.x + bz2.x + a.x)));
    float zy = 1.f / (1.f + __expf(-(z0.y + bz2.y + a.y)));
    *(float2*)&g_zb[gw * 64 + co] = make_float2(zx, zy);
}

// ---------------- prop2: gather U3; fused tanh + GRU update ----------------
__global__ void k_prop2(const float* __restrict__ h, const float* __restrict__ bh,
                        float* __restrict__ out) {
    int gw = (blockIdx.x * blockDim.x + threadIdx.x) >> 5;
    int lane = threadIdx.x & 31;
    if (gw >= N_NODES) return;
    float2 a = gather_row((const uint32_t*)g_Vg, g_rowoff[gw], g_rowend[gw], lane, Idx32());
    int co = lane * 2;
    float2 h0 = *(const float2*)&g_Vs[(size_t)gw * 64 + co];
    float2 bh2 = *(const float2*)&bh[co];
    float htx = tanhf(h0.x + bh2.x + a.x);
    float hty = tanhf(h0.y + bh2.y + a.y);
    float2 z = *(const float2*)&g_zb[gw * 64 + co];
    float2 hh = *(const float2*)&h[gw * 64 + co];
    float ox = (1.f - z.x) * hh.x + z.x * htx;
    float oy = (1.f - z.y) * hh.y + z.y * hty;
    *(float2*)&out[gw * 64 + co] = make_float2(ox, oy);
}

// ---------------- launch: fork chain B; overlap prop1z with GEMM2 ----------------
extern "C" void kernel_launch(void* const* d_in, const int* in_sizes, int n_in,
                              void* d_out, int out_size) {
    const float* x  = (const float*)d_in[0];
    const void*  ei = d_in[1];
    const float* ew = (const float*)d_in[2];
    const float* h  = (const float*)d_in[3];
    const float* Wz = (const float*)d_in[4];
    const float* bz = (const float*)d_in[5];
    const float* Wr = (const float*)d_in[6];
    const float* br = (const float*)d_in[7];
    const float* Wh = (const float*)d_in[8];
    const float* bh = (const float*)d_in[9];
    float* out = (float*)d_out;

    const int TB = 256;
    const int nb_nodes = (N_NODES + TB - 1) / TB;
    const int nb_edge2 = (N_EDGES / 2 + TB - 1) / TB;
    const int nb_rows  = (N_NODES + 7) / 8;        // 8 warps/block, 1 warp/row
    const int nb_tile  = (N_NODES + 127) / 128;    // 391

    const int SMEM_GEMM = 131072;
    cudaFuncSetAttribute(k_mgemm, cudaFuncAttributeMaxDynamicSharedMemorySize, SMEM_GEMM);

    cudaStream_t s2 = g_fork.s2;   // 0 -> serial fallback (still correct)
    bool fork = (s2 != 0) && (g_fork.evF != 0) && (g_fork.evJ != 0) &&
                (g_fork.evR != 0) && (g_fork.evZ != 0);

    if (fork) {
        cudaEventRecord(g_fork.evF, 0);
        cudaStreamWaitEvent(s2, g_fork.evF, 0);
        // chain B on s2: weight prep -> GEMM1 (independent of edge chain)
        k_wprep<<<192, TB, 0, s2>>>(Wz, Wr, Wh);
        k_mgemm<<<dim3(nb_tile, 2), TB, SMEM_GEMM, s2>>>(x, h, 0, /*wb=*/0, /*dst=*/0);
        cudaEventRecord(g_fork.evJ, s2);
        // chain A on null stream
        k_init<<<nb_nodes, TB>>>(ei);
        k_deg<<<nb_edge2, TB>>>(ei, ew);
        k_blockscan<<<nb_nodes, TB>>>();
        k_csr<<<nb_edge2, TB>>>(ei, ew);
        cudaStreamWaitEvent(0, g_fork.evJ, 0);
        // critical path: r-gate -> GEMM2; z-gate hides under GEMM2 on s2
        k_prop1r<<<nb_rows, TB>>>(h, br);
        cudaEventRecord(g_fork.evR, 0);
        cudaStreamWaitEvent(s2, g_fork.evR, 0);
        k_prop1z<<<nb_rows, TB, 0, s2>>>(bz);
        cudaEventRecord(g_fork.evZ, s2);
        k_mgemm<<<dim3(nb_tile, 1), TB, SMEM_GEMM>>>(x, nullptr, 1, /*wb=*/4, /*dst=*/1);
        cudaStreamWaitEvent(0, g_fork.evZ, 0);
        k_prop2<<<nb_rows, TB>>>(h, bh, out);
    } else {
        k_wprep<<<192, TB>>>(Wz, Wr, Wh);
        k_init<<<nb_nodes, TB>>>(ei);
        k_deg<<<nb_edge2, TB>>>(ei, ew);
        k_blockscan<<<nb_nodes, TB>>>();
        k_csr<<<nb_edge2, TB>>>(ei, ew);
        k_mgemm<<<dim3(nb_tile, 2), TB, SMEM_GEMM>>>(x, h, 0, /*wb=*/0, /*dst=*/0);
        k_prop1r<<<nb_rows, TB>>>(h, br);
        k_prop1z<<<nb_rows, TB>>>(bz);
        k_mgemm<<<dim3(nb_tile, 1), TB, SMEM_GEMM>>>(x, nullptr, 1, /*wb=*/4, /*dst=*/1);
        k_prop2<<<nb_rows, TB>>>(h, bh, out);
    }
}

// round 17
// speedup vs baseline: 1.0072x; 1.0072x over previous
#include <cuda_runtime.h>
#include <cuda_bf16.h>
#include <cuda_fp16.h>
#include <cstdint>

#define N_NODES 50000
#define N_EDGES 800000

// ---------------- scratch (static device globals; no allocation) ----------------
__device__ unsigned long long g_degcnt[N_NODES];  // {count:24 | sum_w fixed 2^-32:40}
__device__ float g_dinv[N_NODES];
__device__ int   g_rowoff[N_NODES];
__device__ int   g_rowend[N_NODES];
__device__ int   g_cursor[N_NODES];
__device__ uint32_t g_epack[N_EDGES];    // {col:16 | lw:fp16}, lw = -w*dinv_r*dinv_c
__device__ float g_Us[N_NODES * 128];    // f32 self channels [Z0 | R0]
__device__ uint32_t g_Ug1[N_NODES * 32]; // fp16 pairs, U1 (z-gather), 128B/node
__device__ uint32_t g_Ug2[N_NODES * 32]; // fp16 pairs, U2 (r-gather), 128B/node
__device__ float g_Vs[N_NODES * 64];     // f32 self [H0]
__device__ __half g_Vg[N_NODES * 64];    // fp16 gathered [U3]
__device__ float g_zb[N_NODES * 64];
__device__ float g_rhb[N_NODES * 64];
__device__ __nv_bfloat16 g_Wbhi[6 * 64 * 128];  // [mat][n][k] transposed weights, bf16 hi
__device__ __nv_bfloat16 g_Wblo[6 * 64 * 128];  // bf16 residual
__device__ int   g_is64;
__device__ int   g_counter;

// ---------------- host-side stream/event objects (created at load; host-only) ----
struct ForkCtx {
    cudaStream_t s2 = 0;
    cudaEvent_t evF = 0, evJ = 0, evR = 0, evZ = 0;
    ForkCtx() {
        if (cudaStreamCreateWithFlags(&s2, cudaStreamNonBlocking) != cudaSuccess) s2 = 0;
        cudaEventCreateWithFlags(&evF, cudaEventDisableTiming);
        cudaEventCreateWithFlags(&evJ, cudaEventDisableTiming);
        cudaEventCreateWithFlags(&evR, cudaEventDisableTiming);
        cudaEventCreateWithFlags(&evZ, cudaEventDisableTiming);
    }
};
static ForkCtx g_fork;

// ---------------- helpers ----------------
__device__ __forceinline__ uint32_t smem_u32(const void* p) {
    uint32_t a;
    asm("{ .reg .u64 t; cvta.to.shared.u64 t, %1; cvt.u32.u64 %0, t; }" : "=r"(a) : "l"(p));
    return a;
}
__device__ __forceinline__ uint32_t pack_bf16x2(float lo, float hi) {
    __nv_bfloat162 t = __floats2bfloat162_rn(lo, hi);
    return *(uint32_t*)&t;
}
__device__ __forceinline__ uint32_t pack_half2(float a, float b) {
    __half2 t = __floats2half2_rn(a, b);
    return *(uint32_t*)&t;
}
__device__ __forceinline__ float2 unpack_half2(uint32_t v) {
    return __half22float2(*(__half2*)&v);
}
__device__ __forceinline__ float ew_f(uint32_t E) {
    return __half2float(__ushort_as_half((unsigned short)(E & 0xFFFF)));
}
__device__ __forceinline__ void ldsm4(uint32_t a[4], uint32_t addr) {
    asm volatile("ldmatrix.sync.aligned.m8n8.x4.shared.b16 {%0,%1,%2,%3}, [%4];"
                 : "=r"(a[0]), "=r"(a[1]), "=r"(a[2]), "=r"(a[3]) : "r"(addr));
}
__device__ __forceinline__ void mma_bf16(float c[4], const uint32_t a[4], const uint32_t b[2]) {
    asm volatile("mma.sync.aligned.m16n8k16.row.col.f32.bf16.bf16.f32 "
                 "{%0,%1,%2,%3}, {%4,%5,%6,%7}, {%8,%9}, {%0,%1,%2,%3};"
                 : "+f"(c[0]), "+f"(c[1]), "+f"(c[2]), "+f"(c[3])
                 : "r"(a[0]), "r"(a[1]), "r"(a[2]), "r"(a[3]), "r"(b[0]), "r"(b[1]));
}
__device__ __forceinline__ int edge_idx(const void* ei, int pos) {
    if (g_is64) return (int)((const long long*)ei)[pos];
    return ((const int*)ei)[pos];
}

// ---------------- chain A kernel 1: zero accumulators + sniff index dtype ----------------
__global__ void k_init(const void* ei) {
    int i = blockIdx.x * 256 + threadIdx.x;
    if (i < N_NODES) g_degcnt[i] = 0ull;
    if (i == 0) {
        g_counter = 0;
        const int* p = (const int*)ei;
        int nz = 0;
#pragma unroll 8
        for (int j = 0; j < 256; j++) nz |= p[2 * j + 1];
        g_is64 = (nz == 0) ? 1 : 0;
    }
}

// ---------------- chain B kernel 1: weight transpose + split to bf16 hi/lo ----------------
__global__ void k_wprep(const float* __restrict__ Wz, const float* __restrict__ Wr,
                        const float* __restrict__ Wh) {
    int i = blockIdx.x * 256 + threadIdx.x;
    if (i >= 6 * 8192) return;
    int m = i >> 13;
    int r = i & 8191;
    int n = r >> 7;
    int k = r & 127;
    const float* W = (m < 2) ? Wz : (m < 4) ? Wr : Wh;
    float v = W[(m & 1) * 8192 + k * 64 + n];
    __nv_bfloat16 hi = __float2bfloat16(v);
    g_Wbhi[i] = hi;
    g_Wblo[i] = __float2bfloat16(v - __bfloat162float(hi));
}

// ---------------- chain A kernel 2: packed degree+count, 2 edges/thread ----------------
__global__ void k_deg(const void* ei, const float* __restrict__ w) {
    int e = (blockIdx.x * blockDim.x + threadIdx.x) * 2;
    if (e >= N_EDGES) return;
    int r0 = edge_idx(ei, e);
    float w0 = w[e];
    unsigned long long v0 = (1ull << 40) | (unsigned long long)(w0 * 4294967296.0f);
    if (e + 1 < N_EDGES) {
        int r1 = edge_idx(ei, e + 1);
        float w1 = w[e + 1];
        unsigned long long v1 = (1ull << 40) | (unsigned long long)(w1 * 4294967296.0f);
        atomicAdd(&g_degcnt[r0], v0);
        atomicAdd(&g_degcnt[r1], v1);
    } else {
        atomicAdd(&g_degcnt[r0], v0);
    }
}

// ---------------- chain A kernel 3: dinv + unordered segment assignment ----------------
__global__ void k_blockscan() {
    int i = blockIdx.x * 256 + threadIdx.x;
    int lane = threadIdx.x & 31, w = threadIdx.x >> 5;
    int v = 0;
    if (i < N_NODES) {
        unsigned long long dc = g_degcnt[i];
        v = (int)(dc >> 40);
        float d = (float)(dc & 0xFFFFFFFFFFull) * (1.0f / 4294967296.0f);
        g_dinv[i] = (d > 0.f) ? rsqrtf(d) : 0.f;
    }
    int s = v;
#pragma unroll
    for (int o = 1; o < 32; o <<= 1) {
        int t = __shfl_up_sync(0xFFFFFFFFu, s, o);
        if (lane >= o) s += t;
    }
    __shared__ int wsum[8];
    __shared__ int base;
    if (lane == 31) wsum[w] = s;
    __syncthreads();
    if (w == 0 && lane < 8) {
        int t = wsum[lane];
#pragma unroll
        for (int o = 1; o < 8; o <<= 1) {
            int u = __shfl_up_sync(0xFFu, t, o);
            if (lane >= o) t += u;
        }
        wsum[lane] = t;
        if (lane == 7) base = atomicAdd(&g_counter, t);
    }
    __syncthreads();
    int excl = s - v + ((w > 0) ? wsum[w - 1] : 0);
    if (i < N_NODES) {
        int st = base + excl;
        g_rowoff[i] = st;
        g_cursor[i] = st;
        g_rowend[i] = st + v;
    }
}

// ---------------- chain A kernel 4: CSR scatter, 2 edges/thread; norm folded into lw ----
__global__ void k_csr(const void* ei, const float* __restrict__ w) {
    int e = (blockIdx.x * blockDim.x + threadIdx.x) * 2;
    if (e >= N_EDGES) return;
    int r0 = edge_idx(ei, e);
    int c0 = edge_idx(ei, N_EDGES + e);
    float lw0 = -w[e] * g_dinv[r0] * g_dinv[c0];
    if (e + 1 < N_EDGES) {
        int r1 = edge_idx(ei, e + 1);
        int c1 = edge_idx(ei, N_EDGES + e + 1);
        float lw1 = -w[e + 1] * g_dinv[r1] * g_dinv[c1];
        int p0 = atomicAdd(&g_cursor[r0], 1);
        int p1 = atomicAdd(&g_cursor[r1], 1);
        g_epack[p0] = ((uint32_t)c0 << 16) | (uint32_t)__half_as_ushort(__float2half(lw0));
        g_epack[p1] = ((uint32_t)c1 << 16) | (uint32_t)__half_as_ushort(__float2half(lw1));
    } else {
        int p0 = atomicAdd(&g_cursor[r0], 1);
        g_epack[p0] = ((uint32_t)c0 << 16) | (uint32_t)__half_as_ushort(__float2half(lw0));
    }
}

// ---------------- mma.sync bf16-split GEMM: 128 rows x 128 cols x K=128 per CTA ----
__global__ void __launch_bounds__(256, 1) k_mgemm(
    const float* __restrict__ src0, const float* __restrict__ src1x, int use_rhb,
    int wb, int dst_sel) {
    extern __shared__ char sm[];
    const int AH = 0, AL = 32768, BH = 65536, BL = 98304;  // each 128 x 256B
    const int tid = threadIdx.x;
    const int lane = tid & 31, w = tid >> 5;
    const int rowBase = blockIdx.x * 128;
    const float* src1 = use_rhb ? g_rhb : src1x;
    const int matBase = wb + blockIdx.y * 2;

    // ---- load A ----
    {
        int row = tid & 127, half = tid >> 7;
        int gr = rowBase + row;
        const float* s = half ? src1 : src0;
        const float4* sp = (const float4*)(s + (size_t)gr * 64);
        char* ah = sm + AH + row * 256;
        char* al = sm + AL + row * 256;
        int rsw = row & 7;
#pragma unroll
        for (int i = 0; i < 8; i++) {
            float4 v0 = make_float4(0.f, 0.f, 0.f, 0.f), v1 = v0;
            if (gr < N_NODES) { v0 = sp[2 * i]; v1 = sp[2 * i + 1]; }
            int kc = half * 8 + i;
            int off = ((kc ^ rsw) << 4);
            uint4 hi, lo;
            hi.x = pack_bf16x2(v0.x, v0.y); hi.y = pack_bf16x2(v0.z, v0.w);
            hi.z = pack_bf16x2(v1.x, v1.y); hi.w = pack_bf16x2(v1.z, v1.w);
            float rx = v0.x - __bfloat162float(__float2bfloat16(v0.x));
            float ry = v0.y - __bfloat162float(__float2bfloat16(v0.y));
            float rz = v0.z - __bfloat162float(__float2bfloat16(v0.z));
            float rw = v0.w - __bfloat162float(__float2bfloat16(v0.w));
            lo.x = pack_bf16x2(rx, ry); lo.y = pack_bf16x2(rz, rw);
            rx = v1.x - __bfloat162float(__float2bfloat16(v1.x));
            ry = v1.y - __bfloat162float(__float2bfloat16(v1.y));
            rz = v1.z - __bfloat162float(__float2bfloat16(v1.z));
            rw = v1.w - __bfloat162float(__float2bfloat16(v1.w));
            lo.z = pack_bf16x2(rx, ry); lo.w = pack_bf16x2(rz, rw);
            *(uint4*)(ah + off) = hi;
            *(uint4*)(al + off) = lo;
        }
    }
    // ---- load B ----
#pragma unroll
    for (int j = 0; j < 8; j++) {
        int idx = tid + j * 256;
        int mat = idx >> 10, rest = idx & 1023;
        int n = rest >> 4, kc = rest & 15;
        int nn = mat * 64 + n;
        size_t gsi = (size_t)(matBase + mat) * 8192 + n * 128 + kc * 8;
        uint4 hv = *(const uint4*)(g_Wbhi + gsi);
        uint4 lv = *(const uint4*)(g_Wblo + gsi);
        int off = nn * 256 + (((kc ^ (nn & 7))) << 4);
        *(uint4*)(sm + BH + off) = hv;
        *(uint4*)(sm + BL + off) = lv;
    }
    __syncthreads();

    // ---- per-warp tile: rows (w&3)*32, mat = w>>2 ----
    const int Rw = (w & 3) * 32;
    const int matSel = w >> 2;
    const int NBw = matSel * 64;
    const uint32_t smb = smem_u32(sm);
    const int tile = lane >> 3, l7 = lane & 7;
    int a_kbit = tile >> 1;
    int a_row0 = Rw + ((tile & 1) << 3) + l7;
    int a_row1 = a_row0 + 16;
    uint32_t aBase0 = smb + AH + a_row0 * 256, aSw0 = (uint32_t)(a_row0 & 7);
    uint32_t aBase1 = smb + AH + a_row1 * 256, aSw1 = (uint32_t)(a_row1 & 7);
    int b_kbit = tile & 1;
    int b_nloc = ((tile >> 1) << 3) + l7;
    uint32_t bBase[4], bSw[4];
#pragma unroll
    for (int ng = 0; ng < 4; ng++) {
        int n = NBw + ng * 16 + b_nloc;
        bBase[ng] = smb + BH + n * 256;
        bSw[ng] = (uint32_t)(n & 7);
    }

    float C[2][4][2][4];
#pragma unroll
    for (int a = 0; a < 2; a++)
#pragma unroll
        for (int b = 0; b < 4; b++)
#pragma unroll
            for (int c = 0; c < 2; c++)
#pragma unroll
                for (int d = 0; d < 4; d++) C[a][b][c][d] = 0.f;

#pragma unroll
    for (int ks = 0; ks < 8; ks++) {
        int ks2 = ks * 2;
        uint32_t akc = (uint32_t)((ks2 + a_kbit));
        uint32_t bkc = (uint32_t)((ks2 + b_kbit));
        uint32_t Ah[2][4], Al[2][4];
        ldsm4(Ah[0], aBase0 + ((akc ^ aSw0) << 4));
        ldsm4(Ah[1], aBase1 + ((akc ^ aSw1) << 4));
        ldsm4(Al[0], aBase0 + 32768 + ((akc ^ aSw0) << 4));
        ldsm4(Al[1], aBase1 + 32768 + ((akc ^ aSw1) << 4));
        uint32_t Bh[4][4], Bl[4][4];
#pragma unroll
        for (int ng = 0; ng < 4; ng++) {
            ldsm4(Bh[ng], bBase[ng] + ((bkc ^ bSw[ng]) << 4));
            ldsm4(Bl[ng], bBase[ng] + 32768 + ((bkc ^ bSw[ng]) << 4));
        }
#pragma unroll
        for (int mt = 0; mt < 2; mt++)
#pragma unroll
            for (int ng = 0; ng < 4; ng++) {
                mma_bf16(C[mt][ng][0], Ah[mt], &Bh[ng][0]);
                mma_bf16(C[mt][ng][1], Ah[mt], &Bh[ng][2]);
                mma_bf16(C[mt][ng][0], Ah[mt], &Bl[ng][0]);
                mma_bf16(C[mt][ng][1], Ah[mt], &Bl[ng][2]);
                mma_bf16(C[mt][ng][0], Al[mt], &Bh[ng][0]);
                mma_bf16(C[mt][ng][1], Al[mt], &Bh[ng][2]);
            }
    }

    // ---- epilogue: self -> f32; gathered -> fp16 (by selects Ug1/Ug2 for GEMM1) ----
    {
        int by = blockIdx.y;
        int ldS = dst_sel ? 64 : 128;
        float* fdst = dst_sel ? g_Vs : g_Us;
        uint32_t* ug = (by == 0) ? g_Ug1 : g_Ug2;
        int colBase = by * 64;
        int q = lane >> 2, tg = lane & 3;
#pragma unroll
        for (int mt = 0; mt < 2; mt++) {
            int r0 = rowBase + Rw + mt * 16 + q;
#pragma unroll
            for (int ng = 0; ng < 4; ng++)
#pragma unroll
                for (int sub = 0; sub < 2; sub++) {
                    int lcol = ng * 16 + sub * 8 + tg * 2;
                    if (matSel == 0) {
                        float* d0 = &fdst[(size_t)r0 * ldS + colBase + lcol];
                        if (r0 < N_NODES)
                            *(float2*)d0 = make_float2(C[mt][ng][sub][0], C[mt][ng][sub][1]);
                        if (r0 + 8 < N_NODES)
                            *(float2*)(d0 + 8 * ldS) = make_float2(C[mt][ng][sub][2], C[mt][ng][sub][3]);
                    } else if (dst_sel == 0) {
                        uint32_t* d0 = &ug[(size_t)r0 * 32 + (lcol >> 1)];
                        if (r0 < N_NODES)
                            d0[0] = pack_half2(C[mt][ng][sub][0], C[mt][ng][sub][1]);
                        if (r0 + 8 < N_NODES)
                            d0[8 * 32] = pack_half2(C[mt][ng][sub][2], C[mt][ng][sub][3]);
                    } else {
                        __half* d0 = &g_Vg[(size_t)r0 * 64 + lcol];
                        if (r0 < N_NODES)
                            *(uint32_t*)d0 = pack_half2(C[mt][ng][sub][0], C[mt][ng][sub][1]);
                        if (r0 + 8 < N_NODES)
                            *(uint32_t*)(d0 + 8 * 64) = pack_half2(C[mt][ng][sub][2], C[mt][ng][sub][3]);
                    }
                }
        }
    }
}

// ---------------- generic 8x-unrolled gather core (one 128B line per node) ----------
template <typename F>
__device__ __forceinline__ float2 gather_row(const uint32_t* __restrict__ buf,
                                             int s, int e, int lane, F idx_of) {
    float ax = 0.f, ay = 0.f;
    int i = s;
    for (; i + 8 <= e; i += 8) {
        uint32_t E[8], V[8];
#pragma unroll
        for (int j = 0; j < 8; j++) E[j] = g_epack[i + j];
#pragma unroll
        for (int j = 0; j < 8; j++) V[j] = buf[idx_of(E[j]) + lane];
#pragma unroll
        for (int j = 0; j < 8; j++) {
            float w = ew_f(E[j]);
            float2 u = unpack_half2(V[j]);
            ax += w * u.x; ay += w * u.y;
        }
    }
    if (i + 4 <= e) {
        uint32_t E[4], V[4];
#pragma unroll
        for (int j = 0; j < 4; j++) E[j] = g_epack[i + j];
#pragma unroll
        for (int j = 0; j < 4; j++) V[j] = buf[idx_of(E[j]) + lane];
#pragma unroll
        for (int j = 0; j < 4; j++) {
            float w = ew_f(E[j]);
            float2 u = unpack_half2(V[j]);
            ax += w * u.x; ay += w * u.y;
        }
        i += 4;
    }
    for (; i < e; i++) {
        uint32_t E = g_epack[i];
        uint32_t v = buf[idx_of(E) + lane];
        float w = ew_f(E);
        float2 u = unpack_half2(v);
        ax += w * u.x; ay += w * u.y;
    }
    return make_float2(ax, ay);
}

struct Idx32 { __device__ size_t operator()(uint32_t E) const { return (size_t)(E >> 16) * 32; } };

// ---------------- prop1r: gather U2 only -> r gate -> rhb (critical path) ----------
__global__ void k_prop1r(const float* __restrict__ h, const float* __restrict__ br) {
    int gw = (blockIdx.x * blockDim.x + threadIdx.x) >> 5;
    int lane = threadIdx.x & 31;
    if (gw >= N_NODES) return;
    float2 a = gather_row(g_Ug2, g_rowoff[gw], g_rowend[gw], lane, Idx32());
    int co = lane * 2;
    float2 r0 = *(const float2*)&g_Us[(size_t)gw * 128 + 64 + co];
    float2 br2 = *(const float2*)&br[co];
    float rx = 1.f / (1.f + __expf(-(r0.x + br2.x + a.x)));
    float ry = 1.f / (1.f + __expf(-(r0.y + br2.y + a.y)));
    float2 hh = *(const float2*)&h[gw * 64 + co];
    *(float2*)&g_rhb[gw * 64 + co] = make_float2(rx * hh.x, ry * hh.y);
}

// ---------------- prop1z: gather U1 only -> z gate (overlaps GEMM2) ----------------
__global__ void k_prop1z(const float* __restrict__ bz) {
    int gw = (blockIdx.x * blockDim.x + threadIdx.x) >> 5;
    int lane = threadIdx.x & 31;
    if (gw >= N_NODES) return;
    float2 a = gather_row(g_Ug1, g_rowoff[gw], g_rowend[gw], lane, Idx32());
    int co = lane * 2;
    float2 z0 = *(const float2*)&g_Us[(size_t)gw * 128 + co];
    float2 bz2 = *(const float2*)&bz[co];
    float zx = 1.f / (1.f + __expf(-(z0.x + bz2.x + a.x)));
    float zy = 1.f / (1.f + __expf(-(z0.y + bz2.y + a.y)));
    *(float2*)&g_zb[gw * 64 + co] = make_float2(zx, zy);
}

// ---------------- prop2: gather U3; fused tanh + GRU update ----------------
__global__ void k_prop2(const float* __restrict__ h, const float* __restrict__ bh,
                        float* __restrict__ out) {
    int gw = (blockIdx.x * blockDim.x + threadIdx.x) >> 5;
    int lane = threadIdx.x & 31;
    if (gw >= N_NODES) return;
    float2 a = gather_row((const uint32_t*)g_Vg, g_rowoff[gw], g_rowend[gw], lane, Idx32());
    int co = lane * 2;
    float2 h0 = *(const float2*)&g_Vs[(size_t)gw * 64 + co];
    float2 bh2 = *(const float2*)&bh[co];
    float htx = tanhf(h0.x + bh2.x + a.x);
    float hty = tanhf(h0.y + bh2.y + a.y);
    float2 z = *(const float2*)&g_zb[gw * 64 + co];
    float2 hh = *(const float2*)&h[gw * 64 + co];
    float ox = (1.f - z.x) * hh.x + z.x * htx;
    float oy = (1.f - z.y) * hh.y + z.y * hty;
    *(float2*)&out[gw * 64 + co] = make_float2(ox, oy);
}

// ---------------- launch: fork chain B; overlap prop1z with GEMM2 ----------------
extern "C" void kernel_launch(void* const* d_in, const int* in_sizes, int n_in,
                              void* d_out, int out_size) {
    const float* x  = (const float*)d_in[0];
    const void*  ei = d_in[1];
    const float* ew = (const float*)d_in[2];
    const float* h  = (const float*)d_in[3];
    const float* Wz = (const float*)d_in[4];
    const float* bz = (const float*)d_in[5];
    const float* Wr = (const float*)d_in[6];
    const float* br = (const float*)d_in[7];
    const float* Wh = (const float*)d_in[8];
    const float* bh = (const float*)d_in[9];
    float* out = (float*)d_out;

    const int TB = 256;
    const int nb_nodes = (N_NODES + TB - 1) / TB;
    const int nb_edge2 = (N_EDGES / 2 + TB - 1) / TB;
    const int nb_rows  = (N_NODES + 7) / 8;        // 8 warps/block, 1 warp/row
    const int nb_tile  = (N_NODES + 127) / 128;    // 391

    const int SMEM_GEMM = 131072;
    cudaFuncSetAttribute(k_mgemm, cudaFuncAttributeMaxDynamicSharedMemorySize, SMEM_GEMM);

    cudaStream_t s2 = g_fork.s2;   // 0 -> serial fallback (still correct)
    bool fork = (s2 != 0) && (g_fork.evF != 0) && (g_fork.evJ != 0) &&
                (g_fork.evR != 0) && (g_fork.evZ != 0);

    if (fork) {
        cudaEventRecord(g_fork.evF, 0);
        cudaStreamWaitEvent(s2, g_fork.evF, 0);
        // chain B on s2: weight prep -> GEMM1 (independent of edge chain)
        k_wprep<<<192, TB, 0, s2>>>(Wz, Wr, Wh);
        k_mgemm<<<dim3(nb_tile, 2), TB, SMEM_GEMM, s2>>>(x, h, 0, /*wb=*/0, /*dst=*/0);
        cudaEventRecord(g_fork.evJ, s2);
        // chain A on null stream
        k_init<<<nb_nodes, TB>>>(ei);
        k_deg<<<nb_edge2, TB>>>(ei, ew);
        k_blockscan<<<nb_nodes, TB>>>();
        k_csr<<<nb_edge2, TB>>>(ei, ew);
        cudaStreamWaitEvent(0, g_fork.evJ, 0);
        // critical path: r-gate -> GEMM2; z-gate hides under GEMM2 on s2
        k_prop1r<<<nb_rows, TB>>>(h, br);
        cudaEventRecord(g_fork.evR, 0);
        cudaStreamWaitEvent(s2, g_fork.evR, 0);
        k_prop1z<<<nb_rows, TB, 0, s2>>>(bz);
        cudaEventRecord(g_fork.evZ, s2);
        k_mgemm<<<dim3(nb_tile, 1), TB, SMEM_GEMM>>>(x, nullptr, 1, /*wb=*/4, /*dst=*/1);
        cudaStreamWaitEvent(0, g_fork.evZ, 0);
        k_prop2<<<nb_rows, TB>>>(h, bh, out);
    } else {
        k_wprep<<<192, TB>>>(Wz, Wr, Wh);
        k_init<<<nb_nodes, TB>>>(ei);
        k_deg<<<nb_edge2, TB>>>(ei, ew);
        k_blockscan<<<nb_nodes, TB>>>();
        k_csr<<<nb_edge2, TB>>>(ei, ew);
        k_mgemm<<<dim3(nb_tile, 2), TB, SMEM_GEMM>>>(x, h, 0, /*wb=*/0, /*dst=*/0);
        k_prop1r<<<nb_rows, TB>>>(h, br);
        k_prop1z<<<nb_rows, TB>>>(bz);
        k_mgemm<<<dim3(nb_tile, 1), TB, SMEM_GEMM>>>(x, nullptr, 1, /*wb=*/4, /*dst=*/1);
        k_prop2<<<nb_rows, TB>>>(h, bh, out);
    }
}